// round 8
// baseline (speedup 1.0000x reference)
#include <cuda_runtime.h>
#include <cuda_bf16.h>
#include <cstdint>

#define NJ    32
#define TPB   64
#define BPB   64                      // one batch per thread
#define RECW  292                     // 288 + 4 pad words -> conflict-free LDS.128/STS.128
#define SMEM_BYTES (BPB * RECW * 4)   // 74,752 B -> 3 CTAs/SM
#define GRID  444                     // 148 SMs x 3 resident CTAs, persistent

__device__ __forceinline__ void cp_async16(uint32_t s_addr, const void* g_ptr) {
    asm volatile("cp.async.cg.shared.global [%0], [%1], 16;\n"
                 :: "r"(s_addr), "l"(g_ptr));
}

__global__ void __launch_bounds__(TPB)
fk32_kernel(const float* __restrict__ angles,
            const float* __restrict__ offs,
            float* __restrict__ out,
            int batch)
{
    extern __shared__ float s[];          // BPB records of RECW floats
    const int t = threadIdx.x;
    const uint32_t sbase = (uint32_t)__cvta_generic_to_shared(s);

    const int par[NJ] = {-1,0,1,2,3,4,0,6,7,8,9,0,11,12,13,14,12,16,17,18,
                         19,20,19,22,12,24,25,26,27,28,27,30};
    const bool isp[NJ] = {1,1,1,1,1,0,1,1,1,1,0,1,1,1,1,0,
                          1,1,1,1,1,0,1,0,1,1,1,1,1,0,1,0};

    const int ntiles = (batch + BPB - 1) / BPB;   // 4096

    for (int tile = blockIdx.x; tile < ntiles; tile += GRID) {
        const size_t B0 = (size_t)tile * BPB;
        const float4* __restrict__ srcv =
            reinterpret_cast<const float4*>(angles) + B0 * 72;

        // ===== issue ALL loads: 8 commit groups, joint-group-major order ====
        // commit group g = the 9 float4 (144B) slice of group g for all 64
        // records. gmem: 144B contiguous runs at 1152B stride (sector-dense).
        #pragma unroll
        for (int g = 0; g < 8; ++g) {
            #pragma unroll
            for (int i = 0; i < 9; ++i) {
                int e  = t + i * TPB;        // 0..575
                int c  = e / 9;              // record in tile
                int ip = e - c * 9;          // float4 within slice
                int bb = c;                  // clamp for (non-existent) tail
                if (B0 + (size_t)bb >= (size_t)batch) bb = 0;
                cp_async16(sbase + (uint32_t)(bb * RECW + (g * 9 + ip) * 4) * 4u,
                           srcv + ((size_t)bb * 72 + g * 9 + ip));
            }
            asm volatile("cp.async.commit_group;\n" ::: "memory");
        }

        // ===== compute: per-group progressive wait + barrier ================
        float4* recv = reinterpret_cast<float4*>(s + t * RECW);
        float R[NJ][9];
        float P[NJ][3];

        #pragma unroll
        for (int g = 0; g < 8; ++g) {
            // own group-g loads complete; barrier publishes everyone's.
            switch (g) {
                case 0:  asm volatile("cp.async.wait_group 7;" ::: "memory"); break;
                case 1:  asm volatile("cp.async.wait_group 6;" ::: "memory"); break;
                case 2:  asm volatile("cp.async.wait_group 5;" ::: "memory"); break;
                case 3:  asm volatile("cp.async.wait_group 4;" ::: "memory"); break;
                case 4:  asm volatile("cp.async.wait_group 3;" ::: "memory"); break;
                case 5:  asm volatile("cp.async.wait_group 2;" ::: "memory"); break;
                case 6:  asm volatile("cp.async.wait_group 1;" ::: "memory"); break;
                default: asm volatile("cp.async.wait_group 0;" ::: "memory"); break;
            }
            __syncthreads();

            // 9 conflict-free LDS.128: this group's 4 rotation matrices
            float a[36];
            #pragma unroll
            for (int q = 0; q < 9; ++q) {
                float4 v = recv[g * 9 + q];
                a[4*q+0] = v.x; a[4*q+1] = v.y; a[4*q+2] = v.z; a[4*q+3] = v.w;
            }

            #pragma unroll
            for (int jj = 0; jj < 4; ++jj) {
                const int j = g * 4 + jj;
                const float* Aj = &a[jj * 9];
                if (j == 0) {
                    #pragma unroll
                    for (int q = 0; q < 9; ++q) R[0][q] = Aj[q];
                    P[0][0] = 0.f; P[0][1] = 0.f; P[0][2] = 0.f;
                } else {
                    const int p = par[j];
                    const float o0 = __ldg(&offs[j*3+0]);
                    const float o1 = __ldg(&offs[j*3+1]);
                    const float o2 = __ldg(&offs[j*3+2]);
                    #pragma unroll
                    for (int l = 0; l < 3; ++l) {
                        P[j][l] = fmaf(o0, R[p][0*3+l],
                                  fmaf(o1, R[p][1*3+l],
                                  fmaf(o2, R[p][2*3+l], P[p][l])));
                    }
                    if (isp[j]) {
                        #pragma unroll
                        for (int i = 0; i < 3; ++i) {
                            #pragma unroll
                            for (int l = 0; l < 3; ++l) {
                                R[j][i*3+l] = fmaf(Aj[i*3+0], R[p][0*3+l],
                                              fmaf(Aj[i*3+1], R[p][1*3+l],
                                                   Aj[i*3+2] * R[p][2*3+l]));
                            }
                        }
                    }
                }
            }

            // pack positions in place: words [12g,12g+12) belong to input
            // group floor(g/3) <= g, already waited-on and consumed.
            const int j0 = g * 4;
            recv[g*3+0] = make_float4(P[j0+0][0], P[j0+0][1], P[j0+0][2], P[j0+1][0]);
            recv[g*3+1] = make_float4(P[j0+1][1], P[j0+1][2], P[j0+2][0], P[j0+2][1]);
            recv[g*3+2] = make_float4(P[j0+2][2], P[j0+3][0], P[j0+3][1], P[j0+3][2]);
        }
        __syncthreads();   // publish packed positions for coalesced flush

        // ===== coalesced float4 flush (dense 128B lines) ====================
        {
            float4* dstv = reinterpret_cast<float4*>(out) + B0 * 24;
            const float4* sv = reinterpret_cast<const float4*>(s);
            #pragma unroll
            for (int k = 0; k < 24; ++k) {
                int q   = t + k * TPB;       // 0..1535
                int c   = q / 24;
                int off = q - c * 24;
                if (B0 + (size_t)c < (size_t)batch)
                    dstv[q] = sv[c * (RECW / 4) + off];
            }
        }
        __syncthreads();   // flush LDS done before next tile's cp.async lands
    }
}

extern "C" void kernel_launch(void* const* d_in, const int* in_sizes, int n_in,
                              void* d_out, int out_size)
{
    const float* angles = (const float*)d_in[0];
    const float* offs   = (const float*)d_in[1];
    float* out          = (float*)d_out;

    int batch = in_sizes[0] / (NJ * 9);           // 262144

    static bool attr_done = false;
    if (!attr_done) {
        cudaFuncSetAttribute(fk32_kernel,
                             cudaFuncAttributeMaxDynamicSharedMemorySize,
                             SMEM_BYTES);
        attr_done = true;
    }

    fk32_kernel<<<GRID, TPB, SMEM_BYTES>>>(angles, offs, out, batch);
}